// round 5
// baseline (speedup 1.0000x reference)
#include <cuda_runtime.h>
#include <cuda_bf16.h>

// InterLayerTrajectoryFlow: fused streaming diff -> L2-normalize -> causal
// 6-tap weighted sum. fp32 in/out, [B=8, S=8192, D=512].
//
// One block = one (batch, CHUNK-position chunk). 128 threads, one float4 per
// row per thread (D=512 -> 128 float4, perfectly coalesced 2 KB rows).
// Ring of last 6 normalized diffs in registers (shift-register, static idx).
// 3-row-deep software prefetch pipeline (load row t+4 while reducing diff t)
// to keep ~40 KB/SM of loads in flight (> 17 KB latency-BW product).
// Per-diff norm: 5x shfl.bfly warp reduce + 4-way smem combine with ONE
// __syncthreads (double-buffered by parity).

namespace {
constexpr int D      = 512;
constexpr int DV     = D / 4;     // float4 per row = 128
constexpr int CHUNK  = 64;        // positions per block
constexpr int NTHR   = DV;        // 128 threads
constexpr int BATCH  = 8;
}

__device__ __forceinline__ float warp_reduce_add(float v) {
#pragma unroll
    for (int o = 16; o > 0; o >>= 1)
        v += __shfl_xor_sync(0xffffffffu, v, o);
    return v;
}

__device__ __forceinline__ float block_reduce_sum(float v, float* red, int par,
                                                  int wid, int lid) {
    v = warp_reduce_add(v);
    if (lid == 0) red[par * 4 + wid] = v;
    __syncthreads();
    return (red[par * 4 + 0] + red[par * 4 + 1]) +
           (red[par * 4 + 2] + red[par * 4 + 3]);
}

// Compute normalized diff (nxt - cur) / (||nxt-cur|| + 1e-8) while issuing the
// prefetch of row `load_row` (3 rows ahead). Rotates the 4-deep pipeline.
__device__ __forceinline__ float4 step(const float4* __restrict__ base,
                                       int load_row, int lane,
                                       float4& cur, float4& nxt,
                                       float4& f1, float4& f2,
                                       float* red, int par, int wid, int lid) {
    float4 fut = __ldg(&base[(size_t)load_row * DV + lane]);  // prefetch t+4
    float4 d;
    d.x = nxt.x - cur.x; d.y = nxt.y - cur.y;
    d.z = nxt.z - cur.z; d.w = nxt.w - cur.w;
    float ss = d.x * d.x + d.y * d.y + d.z * d.z + d.w * d.w;
    ss = block_reduce_sum(ss, red, par, wid, lid);
    // mag > 1e-6  <=>  mag^2 > 1e-12
    float inv = (ss > 1e-12f) ? (1.0f / (sqrtf(ss) + 1e-8f)) : 0.0f;
    d.x *= inv; d.y *= inv; d.z *= inv; d.w *= inv;
    cur = nxt; nxt = f1; f1 = f2; f2 = fut;
    return d;
}

__global__ void __launch_bounds__(NTHR)
traj_flow_kernel(const float* __restrict__ emb,
                 const int* __restrict__ layer_idx_p,
                 float* __restrict__ out, int S) {
    __shared__ float red[8];

    const int b    = blockIdx.y;
    const int p0   = blockIdx.x * CHUNK;
    const int lane = threadIdx.x;
    const int wid  = lane >> 5;
    const int lid  = lane & 31;

    const float4* base  = reinterpret_cast<const float4*>(emb) + (size_t)b * S * DV;
    float4*       obase = reinterpret_cast<float4*>(out)       + (size_t)b * S * DV;

    const float scale = 0.1f * (1.0f + (float)(*layer_idx_p) * 0.8f);

    // Full-window fused coefficients: scale * exp(-k/5) / (sum + 1e-8)
    float coef[6];
    {
        float wsum = 0.0f;
#pragma unroll
        for (int k = 0; k < 6; ++k) { coef[k] = expf(-(float)k * 0.2f); wsum += coef[k]; }
        const float c = scale / (wsum + 1e-8f);
#pragma unroll
        for (int k = 0; k < 6; ++k) coef[k] *= c;
    }

    float4 z4; z4.x = z4.y = z4.z = z4.w = 0.0f;
    float4 n0 = z4, n1 = z4, n2 = z4, n3 = z4, n4 = z4, n5 = z4;

    const int nout = min(CHUNK, S - p0);

    if (p0 == 0) {
        // ---- slow path: positions 0..nout-1 (handles pos<6 specials) ----
        float4 cur = __ldg(&base[lane]);
        float4 nxt = __ldg(&base[(size_t)1 * DV + lane]);
        float4 f1  = __ldg(&base[(size_t)min(2, S - 1) * DV + lane]);
        float4 f2  = __ldg(&base[(size_t)min(3, S - 1) * DV + lane]);
        for (int t = 0; t <= nout - 2; ++t) {
            const int lr = min(t + 4, S - 1);
            float4 nd = step(base, lr, lane, cur, nxt, f1, f2, red, t & 1, wid, lid);
            n5 = n4; n4 = n3; n3 = n2; n2 = n1; n1 = n0; n0 = nd;
            const int pos = t + 1;
            float4 acc;
            if (pos >= 6) {
                acc.x = coef[0]*n0.x + coef[1]*n1.x + coef[2]*n2.x + coef[3]*n3.x + coef[4]*n4.x + coef[5]*n5.x;
                acc.y = coef[0]*n0.y + coef[1]*n1.y + coef[2]*n2.y + coef[3]*n3.y + coef[4]*n4.y + coef[5]*n5.y;
                acc.z = coef[0]*n0.z + coef[1]*n1.z + coef[2]*n2.z + coef[3]*n3.z + coef[4]*n4.z + coef[5]*n5.z;
                acc.w = coef[0]*n0.w + coef[1]*n1.w + coef[2]*n2.w + coef[3]*n3.w + coef[4]*n4.w + coef[5]*n5.w;
            } else {
                // pos in 1..5: window w = pos, weights exp(-k/(w-1)) (w>1) or exp(-1) (w==1)
                float wk[5] = {0.f, 0.f, 0.f, 0.f, 0.f};
                float wsum = 0.0f;
                if (pos == 1) {
                    wk[0] = 0.36787944117144233f;  // exp(-1), torch.linspace(-1,0,1)
                    wsum  = wk[0];
                } else {
                    const float dn = (float)(pos - 1);
#pragma unroll
                    for (int k = 0; k < 5; ++k) {
                        if (k < pos) { wk[k] = expf(-(float)k / dn); wsum += wk[k]; }
                    }
                }
                const float c = scale / (wsum + 1e-8f);
                acc.x = c * (wk[0]*n0.x + wk[1]*n1.x + wk[2]*n2.x + wk[3]*n3.x + wk[4]*n4.x);
                acc.y = c * (wk[0]*n0.y + wk[1]*n1.y + wk[2]*n2.y + wk[3]*n3.y + wk[4]*n4.y);
                acc.z = c * (wk[0]*n0.z + wk[1]*n1.z + wk[2]*n2.z + wk[3]*n3.z + wk[4]*n4.z);
                acc.w = c * (wk[0]*n0.w + wk[1]*n1.w + wk[2]*n2.w + wk[3]*n3.w + wk[4]*n4.w);
            }
            obase[(size_t)pos * DV + lane] = acc;
        }
        obase[lane] = z4;  // pos 0 -> zeros (out is poisoned, must write)
    } else {
        // ---- fast path: all positions use constant full-window taps ----
        float4 cur = __ldg(&base[(size_t)(p0 - 6) * DV + lane]);
        float4 nxt = __ldg(&base[(size_t)(p0 - 5) * DV + lane]);
        float4 f1  = __ldg(&base[(size_t)(p0 - 4) * DV + lane]);
        float4 f2  = __ldg(&base[(size_t)(p0 - 3) * DV + lane]);
        // prologue: diffs t = p0-6 .. p0-2 fill the ring (no output)
#pragma unroll
        for (int i = 0; i < 5; ++i) {
            const int t = p0 - 6 + i;
            float4 nd = step(base, t + 4, lane, cur, nxt, f1, f2, red, i & 1, wid, lid);
            n5 = n4; n4 = n3; n3 = n2; n2 = n1; n1 = n0; n0 = nd;
        }
        // main: diffs t = p0-1+i  ->  pos = p0+i,  i = 0..nout-1
#pragma unroll 2
        for (int i = 0; i < nout; ++i) {
            const int t  = p0 - 1 + i;
            const int lr = min(t + 4, S - 1);
            float4 nd = step(base, lr, lane, cur, nxt, f1, f2, red, (i + 1) & 1, wid, lid);
            n5 = n4; n4 = n3; n3 = n2; n2 = n1; n1 = n0; n0 = nd;
            float4 acc;
            acc.x = coef[0]*n0.x + coef[1]*n1.x + coef[2]*n2.x + coef[3]*n3.x + coef[4]*n4.x + coef[5]*n5.x;
            acc.y = coef[0]*n0.y + coef[1]*n1.y + coef[2]*n2.y + coef[3]*n3.y + coef[4]*n4.y + coef[5]*n5.y;
            acc.z = coef[0]*n0.z + coef[1]*n1.z + coef[2]*n2.z + coef[3]*n3.z + coef[4]*n4.z + coef[5]*n5.z;
            acc.w = coef[0]*n0.w + coef[1]*n1.w + coef[2]*n2.w + coef[3]*n3.w + coef[4]*n4.w + coef[5]*n5.w;
            obase[(size_t)(p0 + i) * DV + lane] = acc;
        }
    }
}

extern "C" void kernel_launch(void* const* d_in, const int* in_sizes, int n_in,
                              void* d_out, int out_size) {
    const float* emb = (const float*)d_in[0];
    const int*   li  = (const int*)d_in[1];
    float*       out = (float*)d_out;

    const int total = in_sizes[0];
    const int S     = total / (BATCH * D);  // 8192 for the reference shapes

    dim3 grid((S + CHUNK - 1) / CHUNK, BATCH);
    traj_flow_kernel<<<grid, NTHR>>>(emb, li, out, S);
}

// round 6
// speedup vs baseline: 1.0807x; 1.0807x over previous
#include <cuda_runtime.h>
#include <cuda_bf16.h>

// InterLayerTrajectoryFlow: fused streaming diff -> L2-normalize -> causal
// 6-tap weighted sum. fp32 in/out, [B=8, S=8192, D=512].
//
// R5 profile: issue-bound (alu 25.6%, dram 48.6%) from ~36 register-rotation
// MOVs per row. This version: period-6 ring AND period-6 load pipeline with a
// manually unrolled 6-step main loop -> all rotations are register renaming
// (zero MOVs). Norm via rsqrt + first-order 1e-8 correction.

namespace {
constexpr int D      = 512;
constexpr int DV     = D / 4;     // float4 per row = 128
constexpr int CHUNK  = 64;        // positions per block
constexpr int NTHR   = DV;        // 128 threads
constexpr int BATCH  = 8;
}

__device__ __forceinline__ float warp_reduce_add(float v) {
#pragma unroll
    for (int o = 16; o > 0; o >>= 1)
        v += __shfl_xor_sync(0xffffffffu, v, o);
    return v;
}

__device__ __forceinline__ float block_reduce_sum(float v, float* red, int par,
                                                  int wid, int lid) {
    v = warp_reduce_add(v);
    if (lid == 0) red[par * 4 + wid] = v;
    __syncthreads();
    return (red[par * 4 + 0] + red[par * 4 + 1]) +
           (red[par * 4 + 2] + red[par * 4 + 3]);
}

// One diff-step. cur holds row t (consumed, then refilled with row `loadrow`),
// nxt holds row t+1. Writes normalized diff into ring slot `rnew`; optionally
// emits output row `outrow` from taps (rnew=age0, r1..r5 = ages 1..5).
__device__ __forceinline__ void stepf(const float4* __restrict__ base,
                                      float4* __restrict__ obase,
                                      int loadrow, int outrow, int lane,
                                      float4& cur, const float4& nxt,
                                      float4& rnew, const float4& r1,
                                      const float4& r2, const float4& r3,
                                      const float4& r4, const float4& r5,
                                      const float (&cf)[6], float* red,
                                      int par, int wid, int lid, bool wout) {
    float4 d;
    d.x = nxt.x - cur.x; d.y = nxt.y - cur.y;
    d.z = nxt.z - cur.z; d.w = nxt.w - cur.w;
    cur = __ldg(&base[(size_t)loadrow * DV + lane]);  // refill vacated slot (t+6)
    float ss = d.x * d.x + d.y * d.y + d.z * d.z + d.w * d.w;
    ss = block_reduce_sum(ss, red, par, wid, lid);
    // 1/(sqrt(ss)+1e-8) ~= t - 1e-8*t^2, t = rsqrt(ss); gate mag>1e-6.
    float t   = rsqrtf(ss);
    float inv = (ss > 1e-12f) ? fmaf(-1e-8f * t, t, t) : 0.0f;
    rnew.x = d.x * inv; rnew.y = d.y * inv;
    rnew.z = d.z * inv; rnew.w = d.w * inv;
    if (wout) {
        float4 a;
        a.x = cf[0]*rnew.x + cf[1]*r1.x + cf[2]*r2.x + cf[3]*r3.x + cf[4]*r4.x + cf[5]*r5.x;
        a.y = cf[0]*rnew.y + cf[1]*r1.y + cf[2]*r2.y + cf[3]*r3.y + cf[4]*r4.y + cf[5]*r5.y;
        a.z = cf[0]*rnew.z + cf[1]*r1.z + cf[2]*r2.z + cf[3]*r3.z + cf[4]*r4.z + cf[5]*r5.z;
        a.w = cf[0]*rnew.w + cf[1]*r1.w + cf[2]*r2.w + cf[3]*r3.w + cf[4]*r4.w + cf[5]*r5.w;
        obase[(size_t)outrow * DV + lane] = a;
    }
}

__global__ void __launch_bounds__(NTHR)
traj_flow_kernel(const float* __restrict__ emb,
                 const int* __restrict__ layer_idx_p,
                 float* __restrict__ out, int S) {
    __shared__ float red[8];

    const int b    = blockIdx.y;
    const int p0   = blockIdx.x * CHUNK;
    const int lane = threadIdx.x;
    const int wid  = lane >> 5;
    const int lid  = lane & 31;

    const float4* base  = reinterpret_cast<const float4*>(emb) + (size_t)b * S * DV;
    float4*       obase = reinterpret_cast<float4*>(out)       + (size_t)b * S * DV;

    const float scale = 0.1f * (1.0f + (float)(*layer_idx_p) * 0.8f);

    // Full-window fused coefficients: scale * exp(-k/5) / (sum + 1e-8)
    float cf[6];
    {
        float wsum = 0.0f;
#pragma unroll
        for (int k = 0; k < 6; ++k) { cf[k] = expf(-(float)k * 0.2f); wsum += cf[k]; }
        const float c = scale / (wsum + 1e-8f);
#pragma unroll
        for (int k = 0; k < 6; ++k) cf[k] *= c;
    }

    float4 z4; z4.x = z4.y = z4.z = z4.w = 0.0f;
    const int nout = min(CHUNK, S - p0);

    if (p0 == 0) {
        // ---- slow path (8 blocks): generic code with pos<6 specials ----
        float4 n0 = z4, n1 = z4, n2 = z4, n3 = z4, n4 = z4, n5 = z4;
        float4 cur = __ldg(&base[lane]);
        float4 nxt = __ldg(&base[(size_t)1 * DV + lane]);
        for (int tt = 0; tt <= nout - 2; ++tt) {
            float4 d;
            d.x = nxt.x - cur.x; d.y = nxt.y - cur.y;
            d.z = nxt.z - cur.z; d.w = nxt.w - cur.w;
            cur = nxt;
            nxt = __ldg(&base[(size_t)min(tt + 2, S - 1) * DV + lane]);
            float ss = d.x*d.x + d.y*d.y + d.z*d.z + d.w*d.w;
            ss = block_reduce_sum(ss, red, tt & 1, wid, lid);
            float t   = rsqrtf(ss);
            float inv = (ss > 1e-12f) ? fmaf(-1e-8f * t, t, t) : 0.0f;
            d.x *= inv; d.y *= inv; d.z *= inv; d.w *= inv;
            n5 = n4; n4 = n3; n3 = n2; n2 = n1; n1 = n0; n0 = d;
            const int pos = tt + 1;
            float4 acc;
            if (pos >= 6) {
                acc.x = cf[0]*n0.x + cf[1]*n1.x + cf[2]*n2.x + cf[3]*n3.x + cf[4]*n4.x + cf[5]*n5.x;
                acc.y = cf[0]*n0.y + cf[1]*n1.y + cf[2]*n2.y + cf[3]*n3.y + cf[4]*n4.y + cf[5]*n5.y;
                acc.z = cf[0]*n0.z + cf[1]*n1.z + cf[2]*n2.z + cf[3]*n3.z + cf[4]*n4.z + cf[5]*n5.z;
                acc.w = cf[0]*n0.w + cf[1]*n1.w + cf[2]*n2.w + cf[3]*n3.w + cf[4]*n4.w + cf[5]*n5.w;
            } else {
                float wk[5] = {0.f, 0.f, 0.f, 0.f, 0.f};
                float wsum = 0.0f;
                if (pos == 1) {
                    wk[0] = 0.36787944117144233f;  // exp(-1), torch.linspace(-1,0,1)
                    wsum  = wk[0];
                } else {
                    const float dn = (float)(pos - 1);
#pragma unroll
                    for (int k = 0; k < 5; ++k) {
                        if (k < pos) { wk[k] = expf(-(float)k / dn); wsum += wk[k]; }
                    }
                }
                const float c = scale / (wsum + 1e-8f);
                acc.x = c * (wk[0]*n0.x + wk[1]*n1.x + wk[2]*n2.x + wk[3]*n3.x + wk[4]*n4.x);
                acc.y = c * (wk[0]*n0.y + wk[1]*n1.y + wk[2]*n2.y + wk[3]*n3.y + wk[4]*n4.y);
                acc.z = c * (wk[0]*n0.z + wk[1]*n1.z + wk[2]*n2.z + wk[3]*n3.z + wk[4]*n4.z);
                acc.w = c * (wk[0]*n0.w + wk[1]*n1.w + wk[2]*n2.w + wk[3]*n3.w + wk[4]*n4.w);
            }
            obase[(size_t)pos * DV + lane] = acc;
        }
        obase[lane] = z4;  // pos 0 -> zeros (out is poisoned, must write)
    } else {
        // ---- fast path: period-6 pipeline + period-6 ring, manual unroll 6 ----
        // Invariant before step j: pipe slot[(j+m) mod 6] holds row p0-1+j+m.
        float4 P1 = __ldg(&base[(size_t)(p0 - 6) * DV + lane]);
        float4 P2 = __ldg(&base[(size_t)(p0 - 5) * DV + lane]);
        float4 P3 = __ldg(&base[(size_t)(p0 - 4) * DV + lane]);
        float4 P4 = __ldg(&base[(size_t)(p0 - 3) * DV + lane]);
        float4 P5 = __ldg(&base[(size_t)(p0 - 2) * DV + lane]);
        float4 P0 = __ldg(&base[(size_t)(p0 - 1) * DV + lane]);
        float4 R0 = z4, R1 = z4, R2 = z4, R3 = z4, R4 = z4, R5 = z4;

        // prologue j = -5..-1: fill ring slots R1..R5 (no outputs)
        stepf(base, obase, p0 + 0, 0, lane, P1, P2, R1, R0,R0,R0,R0,R0, cf, red, 1, wid, lid, false);
        stepf(base, obase, p0 + 1, 0, lane, P2, P3, R2, R0,R0,R0,R0,R0, cf, red, 0, wid, lid, false);
        stepf(base, obase, p0 + 2, 0, lane, P3, P4, R3, R0,R0,R0,R0,R0, cf, red, 1, wid, lid, false);
        stepf(base, obase, p0 + 3, 0, lane, P4, P5, R4, R0,R0,R0,R0,R0, cf, red, 0, wid, lid, false);
        stepf(base, obase, p0 + 4, 0, lane, P5, P0, R5, R0,R0,R0,R0,R0, cf, red, 1, wid, lid, false);

        // main: step j outputs pos p0+j, loads row p0+5+j (clamped)
        int j = 0;
        for (; j + 6 <= nout; j += 6) {
            const int lr = p0 + 5 + j;
            stepf(base, obase, min(lr + 0, S - 1), p0 + j + 0, lane, P0, P1, R0, R5,R4,R3,R2,R1, cf, red, 0, wid, lid, true);
            stepf(base, obase, min(lr + 1, S - 1), p0 + j + 1, lane, P1, P2, R1, R0,R5,R4,R3,R2, cf, red, 1, wid, lid, true);
            stepf(base, obase, min(lr + 2, S - 1), p0 + j + 2, lane, P2, P3, R2, R1,R0,R5,R4,R3, cf, red, 0, wid, lid, true);
            stepf(base, obase, min(lr + 3, S - 1), p0 + j + 3, lane, P3, P4, R3, R2,R1,R0,R5,R4, cf, red, 1, wid, lid, true);
            stepf(base, obase, min(lr + 4, S - 1), p0 + j + 4, lane, P4, P5, R4, R3,R2,R1,R0,R5, cf, red, 0, wid, lid, true);
            stepf(base, obase, min(lr + 5, S - 1), p0 + j + 5, lane, P5, P0, R5, R4,R3,R2,R1,R0, cf, red, 1, wid, lid, true);
        }
        // remainder (0..5 steps; trip count uniform across the block)
        if (j + 0 < nout) stepf(base, obase, min(p0 + 5 + j, S - 1), p0 + j + 0, lane, P0, P1, R0, R5,R4,R3,R2,R1, cf, red, 0, wid, lid, true);
        if (j + 1 < nout) stepf(base, obase, min(p0 + 6 + j, S - 1), p0 + j + 1, lane, P1, P2, R1, R0,R5,R4,R3,R2, cf, red, 1, wid, lid, true);
        if (j + 2 < nout) stepf(base, obase, min(p0 + 7 + j, S - 1), p0 + j + 2, lane, P2, P3, R2, R1,R0,R5,R4,R3, cf, red, 0, wid, lid, true);
        if (j + 3 < nout) stepf(base, obase, min(p0 + 8 + j, S - 1), p0 + j + 3, lane, P3, P4, R3, R2,R1,R0,R5,R4, cf, red, 1, wid, lid, true);
        if (j + 4 < nout) stepf(base, obase, min(p0 + 9 + j, S - 1), p0 + j + 4, lane, P4, P5, R4, R3,R2,R1,R0,R5, cf, red, 0, wid, lid, true);
    }
}

extern "C" void kernel_launch(void* const* d_in, const int* in_sizes, int n_in,
                              void* d_out, int out_size) {
    const float* emb = (const float*)d_in[0];
    const int*   li  = (const int*)d_in[1];
    float*       out = (float*)d_out;

    const int total = in_sizes[0];
    const int S     = total / (BATCH * D);  // 8192 for the reference shapes

    dim3 grid((S + CHUNK - 1) / CHUNK, BATCH);
    traj_flow_kernel<<<grid, NTHR>>>(emb, li, out, S);
}